// round 8
// baseline (speedup 1.0000x reference)
#include <cuda_runtime.h>
#include <math.h>

#define HWALL 65536
#define BATCH 4

typedef unsigned long long ull;

// ---------------- scratch (device globals; no allocations allowed) ----------
__device__ float g_proj [BATCH * 128 * HWALL];   // input_proj output (lb | gb)
__device__ float g_xp   [BATCH *  64 * HWALL];   // lgce pre-conv output
__device__ float g_resp [BATCH *  64 * HWALL];   // resp; later reused as gate hidden [B,32,HW]
__device__ float g_qkv  [BATCH * 192 * HWALL];   // qkv pre-dw
__device__ float g_qkv2 [BATCH * 192 * HWALL];   // qkv post-dw
__device__ float g_fused[BATCH * 128 * HWALL];   // [attn_out | lgce_out]

__device__ float g_wt_ip  [128 * 128];
__device__ float g_wt_pre [ 64 *  64];
__device__ float g_wt_post[ 64 *  64];
__device__ float g_wt_qkv [ 64 * 192];
__device__ float g_wt_g1  [ 64 *  32];
__device__ float g_wt_po  [128 * 128];

__device__ float g_pooled [BATCH * 64];
__device__ float g_cw     [BATCH * 64];
__device__ float g_respsum[BATCH * 8];
__device__ float g_gatesum;
__device__ float g_gram   [BATCH * 8 * 80];   // per (b,h): 64 gram + 8 qsq + 8 ksq
__device__ float g_attn   [BATCH * 8 * 64];

__device__ __forceinline__ float sigmoidf(float x) {
    return 1.0f / (1.0f + __expf(-x));
}

__device__ __forceinline__ ull pack2(float a, float b) {
    ull r; asm("mov.b64 %0, {%1, %2};" : "=l"(r) : "f"(a), "f"(b)); return r;
}
__device__ __forceinline__ ull fma2(ull a, ull b, ull c) {
    ull d; asm("fma.rn.f32x2 %0, %1, %2, %3;" : "=l"(d) : "l"(a), "l"(b), "l"(c)); return d;
}
__device__ __forceinline__ float2 unpk(ull v) {
    float2 f; asm("mov.b64 {%0, %1}, %2;" : "=f"(f.x), "=f"(f.y) : "l"(v)); return f;
}

__device__ __forceinline__ void cp_async16(void* smem_dst, const void* gptr) {
    unsigned sa = (unsigned)__cvta_generic_to_shared(smem_dst);
    asm volatile("cp.async.ca.shared.global [%0], [%1], 16;" :: "r"(sa), "l"(gptr));
}
__device__ __forceinline__ void cp_commit() {
    asm volatile("cp.async.commit_group;");
}
template<int N>
__device__ __forceinline__ void cp_wait() {
    asm volatile("cp.async.wait_group %0;" :: "n"(N));
}

// ---------------- small setup kernels ----------------------------------------
__global__ void zero_small() {
    int t = blockIdx.x * 256 + threadIdx.x;
    if (t < BATCH * 64) g_pooled[t] = 0.f;
    if (t < BATCH * 8)  g_respsum[t] = 0.f;
    if (t == 0)         g_gatesum = 0.f;
    if (t < BATCH * 8 * 80) g_gram[t] = 0.f;
}

__global__ void transpose_all(const float* __restrict__ ip, const float* __restrict__ pre,
                              const float* __restrict__ post, const float* __restrict__ qkv,
                              const float* __restrict__ g1, const float* __restrict__ po) {
    int i = blockIdx.x * 256 + threadIdx.x;
    if (i < 16384) { int o = i >> 7, c = i & 127; g_wt_ip[c * 128 + o] = ip[i]; return; }
    i -= 16384;
    if (i < 4096)  { int o = i >> 6, c = i & 63;  g_wt_pre[c * 64 + o] = pre[i]; return; }
    i -= 4096;
    if (i < 4096)  { int o = i >> 6, c = i & 63;  g_wt_post[c * 64 + o] = post[i]; return; }
    i -= 4096;
    if (i < 12288) { int o = i >> 6, c = i & 63;  g_wt_qkv[c * 192 + o] = qkv[i]; return; }
    i -= 12288;
    if (i < 2048)  { int o = i >> 6, c = i & 63;  g_wt_g1[c * 32 + o] = g1[i]; return; }
    i -= 2048;
    { int o = i >> 7, c = i & 127; g_wt_po[c * 128 + o] = po[i]; }
}

// ---------------- conv1x1 GEMM v3: packed weights, triple-buffer X -----------
// out[o,p] = sum_c in[c,p]*W[o,c]; wt transposed wt[c*COUT+o].
// Per-element fma2 chain is k-ascending -> bit-identical to R5/R6.
template<int CIN>
__global__ void __launch_bounds__(256) conv1x1_gemm_t(
    const float* __restrict__ in, const float* __restrict__ wt,
    const float* __restrict__ bias, float* __restrict__ out,
    int COUT, long long in_bstride, int in_coff,
    long long out_bstride, int out_coff)
{
    __shared__ ull   Ws2[64 * 64];        // packed (w,w); half of W when CIN=128
    __shared__ float Xs[3][16 * 128];     // triple-buffered pixel tiles
    int b  = blockIdx.z;
    int p0 = blockIdx.x * 128;
    int o0 = blockIdx.y * 64;
    int tid = threadIdx.x;
    const float* inb = in + (size_t)b * in_bstride + (size_t)in_coff * HWALL;

    // load W half 0 (k rows 0..63)
    for (int i = tid; i < 64 * 64; i += 256) {
        int c_ = i >> 6, ol = i & 63;
        int o = o0 + ol;
        float w = (o < COUT && c_ < CIN) ? wt[c_ * COUT + o] : 0.0f;
        Ws2[i] = pack2(w, w);
    }

    int og = tid & 15, pg = tid >> 4;
    int xr = tid >> 4, xc = (tid & 15) * 8;

    constexpr int NC = CIN / 16;
    // prologue: prefetch chunks 0 and 1
    {
        const float* s0 = inb + (size_t)xr * HWALL + p0 + xc;
        cp_async16(&Xs[0][xr * 128 + xc],     s0);
        cp_async16(&Xs[0][xr * 128 + xc + 4], s0 + 4);
        cp_commit();
        if (NC > 1) {
            const float* s1 = inb + (size_t)(16 + xr) * HWALL + p0 + xc;
            cp_async16(&Xs[1][xr * 128 + xc],     s1);
            cp_async16(&Xs[1][xr * 128 + xc + 4], s1 + 4);
            cp_commit();
        }
    }

    ull acc[4][4];
#pragma unroll
    for (int i = 0; i < 4; i++)
#pragma unroll
        for (int j = 0; j < 4; j++) acc[i][j] = 0ull;

#pragma unroll
    for (int c = 0; c < NC; c++) {
        // ensure chunk c has landed (leave at most the 1 newer group pending)
        if (c < NC - 1) cp_wait<1>(); else cp_wait<0>();
        __syncthreads();
        // mid-kernel W reload for CIN=128 (k rows 64..127)
        if (CIN == 128 && c == 4) {
            for (int i = tid; i < 64 * 64; i += 256) {
                int c_ = i >> 6, ol = i & 63;
                int o = o0 + ol;
                float w = (o < COUT) ? wt[(64 + c_) * COUT + o] : 0.0f;
                Ws2[i] = pack2(w, w);
            }
            __syncthreads();
        }
        // prefetch chunk c+2 into buffer (c+2)%3 (held chunk c-1; barrier passed)
        if (c + 2 < NC) {
            const float* src = inb + (size_t)((c + 2) * 16 + xr) * HWALL + p0 + xc;
            cp_async16(&Xs[(c + 2) % 3][xr * 128 + xc],     src);
            cp_async16(&Xs[(c + 2) % 3][xr * 128 + xc + 4], src + 4);
            cp_commit();
        }
        const float* Xc = Xs[c % 3];
        int kbase = (CIN == 128 ? (c & 3) : c) * 16;
#pragma unroll
        for (int k = 0; k < 16; k++) {
            const ull* wp = &Ws2[(kbase + k) * 64 + og * 4];
            ull w0 = wp[0], w1 = wp[1], w2 = wp[2], w3 = wp[3];
            const ull* xp2 = (const ull*)&Xc[k * 128 + pg * 8];
            ull x0 = xp2[0], x1 = xp2[1], x2 = xp2[2], x3 = xp2[3];
            acc[0][0] = fma2(w0, x0, acc[0][0]); acc[0][1] = fma2(w0, x1, acc[0][1]);
            acc[0][2] = fma2(w0, x2, acc[0][2]); acc[0][3] = fma2(w0, x3, acc[0][3]);
            acc[1][0] = fma2(w1, x0, acc[1][0]); acc[1][1] = fma2(w1, x1, acc[1][1]);
            acc[1][2] = fma2(w1, x2, acc[1][2]); acc[1][3] = fma2(w1, x3, acc[1][3]);
            acc[2][0] = fma2(w2, x0, acc[2][0]); acc[2][1] = fma2(w2, x1, acc[2][1]);
            acc[2][2] = fma2(w2, x2, acc[2][2]); acc[2][3] = fma2(w2, x3, acc[2][3]);
            acc[3][0] = fma2(w3, x0, acc[3][0]); acc[3][1] = fma2(w3, x1, acc[3][1]);
            acc[3][2] = fma2(w3, x2, acc[3][2]); acc[3][3] = fma2(w3, x3, acc[3][3]);
        }
    }

    float* outb = out + (size_t)b * out_bstride + (size_t)out_coff * HWALL;
#pragma unroll
    for (int i = 0; i < 4; i++) {
        int o = o0 + og * 4 + i;
        if (o < COUT) {
            float bv = bias ? bias[o] : 0.0f;
            float2 u0 = unpk(acc[i][0]), u1 = unpk(acc[i][1]);
            float2 u2 = unpk(acc[i][2]), u3 = unpk(acc[i][3]);
            float4 r0 = make_float4(u0.x + bv, u0.y + bv, u1.x + bv, u1.y + bv);
            float4 r1 = make_float4(u2.x + bv, u2.y + bv, u3.x + bv, u3.y + bv);
            float* dst = outb + (size_t)o * HWALL + p0 + pg * 8;
            *(float4*)(dst)     = r0;
            *(float4*)(dst + 4) = r1;
        }
    }
}

// ---------------- LGCE pooling (R2-exact) -------------------------------------
__global__ void pool_mean() {
    int bc = blockIdx.x;   // 0..255 = b*64+c
    const float* p = g_xp + (size_t)bc * HWALL;
    float s = 0.f;
    for (int i = threadIdx.x; i < HWALL / 4; i += 256) {
        float4 v = ((const float4*)p)[i];
        s += v.x + v.y + v.z + v.w;
    }
    __shared__ float sm[256];
    sm[threadIdx.x] = s; __syncthreads();
    for (int st = 128; st; st >>= 1) {
        if (threadIdx.x < st) sm[threadIdx.x] += sm[threadIdx.x + st];
        __syncthreads();
    }
    if (threadIdx.x == 0) g_pooled[bc] = sm[0];
}

__global__ void compute_cw(const float* __restrict__ w1, const float* __restrict__ b1,
                           const float* __restrict__ w2, const float* __restrict__ b2) {
    int t = threadIdx.x;               // 256 = 4*8*8
    int b = t >> 6, gc = t & 63, g = gc >> 3, c = gc & 7;
    float hid[2];
#pragma unroll
    for (int hh = 0; hh < 2; hh++) {
        float s = b1[g * 2 + hh];
#pragma unroll
        for (int cc = 0; cc < 8; cc++)
            s += (g_pooled[b * 64 + g * 8 + cc] * (1.0f / HWALL)) * w1[(g * 2 + hh) * 8 + cc];
        hid[hh] = fmaxf(s, 0.0f);
    }
    float s2 = b2[g * 8 + c] + hid[0] * w2[(g * 8 + c) * 2] + hid[1] * w2[(g * 8 + c) * 2 + 1];
    g_cw[b * 64 + gc] = sigmoidf(s2);
}

// ---------------- resp: compute, store (g_resp), reduce sums (R2-exact) ------
__global__ void __launch_bounds__(256) resp_kernel(const float* __restrict__ sw,
                                                   const float* __restrict__ sb) {
    int b = blockIdx.y;
    int p = blockIdx.x * 256 + threadIdx.x;
    __shared__ float cws[64], sws[64], sbs[8];
    if (threadIdx.x < 64) { cws[threadIdx.x] = g_cw[b * 64 + threadIdx.x]; sws[threadIdx.x] = sw[threadIdx.x]; }
    if (threadIdx.x < 8) sbs[threadIdx.x] = sb[threadIdx.x];
    __syncthreads();

    float rsum[8];
#pragma unroll
    for (int g = 0; g < 8; g++) {
        float xc[8];
        float sa = sbs[g];
#pragma unroll
        for (int c = 0; c < 8; c++) {
            float v = g_xp[((size_t)b * 64 + g * 8 + c) * HWALL + p];
            xc[c] = v * cws[g * 8 + c];
            sa += sws[g * 8 + c] * xc[c];
        }
        float sp = sigmoidf(sa);
        float rs = 0.f;
#pragma unroll
        for (int c = 0; c < 8; c++) {
            float r = sigmoidf(xc[c] * sp);
            g_resp[((size_t)b * 64 + g * 8 + c) * HWALL + p] = r;
            rs += r;
        }
        rsum[g] = rs;
    }
#pragma unroll
    for (int g = 0; g < 8; g++)
#pragma unroll
        for (int off = 16; off > 0; off >>= 1)
            rsum[g] += __shfl_down_sync(0xffffffffu, rsum[g], off);

    __shared__ float red[8][8];
    int w = threadIdx.x >> 5, l = threadIdx.x & 31;
    if (l == 0)
#pragma unroll
        for (int g = 0; g < 8; g++) red[w][g] = rsum[g];
    __syncthreads();
    if (threadIdx.x < 8) {
        float s = 0.f;
#pragma unroll
        for (int ww = 0; ww < 8; ww++) s += red[ww][threadIdx.x];
        atomicAdd(&g_respsum[b * 8 + threadIdx.x], s);
    }
}

// ---------------- masked post-conv + residual (reads g_resp; FFMA2) ----------
__global__ void __launch_bounds__(256) conv1x1_maskres(const float* __restrict__ bias)
{
    __shared__ float Ws[64 * 64];
    __shared__ float Xm[64 * 64];
    __shared__ float thr_s[8];
    int b  = blockIdx.z;
    int p0 = blockIdx.x * 64;
    int tid = threadIdx.x;

    if (tid < 8) thr_s[tid] = g_respsum[b * 8 + tid] * (1.0f / (8.0f * HWALL));
    for (int i = tid; i < 64 * 64; i += 256) {
        int c = i >> 6, o = i & 63;
        Ws[i] = g_wt_post[c * 64 + o];
    }
    __syncthreads();

    {
        int xr = tid >> 4, xc4 = (tid & 15) * 4;
        const float* xpb = g_xp   + (size_t)b * 64 * HWALL;
        const float* rsb = g_resp + (size_t)b * 64 * HWALL;
#pragma unroll
        for (int cc = 0; cc < 4; cc++) {
            int ch = cc * 16 + xr;
            float t = thr_s[ch >> 3];
            float4 xv = *(const float4*)(xpb + (size_t)ch * HWALL + p0 + xc4);
            float4 rv = *(const float4*)(rsb + (size_t)ch * HWALL + p0 + xc4);
            xv.x *= (rv.x > t) ? 1.0f : rv.x;
            xv.y *= (rv.y > t) ? 1.0f : rv.y;
            xv.z *= (rv.z > t) ? 1.0f : rv.z;
            xv.w *= (rv.w > t) ? 1.0f : rv.w;
            *(float4*)&Xm[ch * 64 + xc4] = xv;
        }
    }
    __syncthreads();

    int og = tid & 15, pg = tid >> 4;
    ull acc[4][2];
#pragma unroll
    for (int i = 0; i < 4; i++) { acc[i][0] = 0ull; acc[i][1] = 0ull; }

#pragma unroll 8
    for (int k = 0; k < 64; k++) {
        float4 wv = *(const float4*)&Ws[k * 64 + og * 4];
        const ull* xp2 = (const ull*)&Xm[k * 64 + pg * 4];
        ull x0 = xp2[0], x1 = xp2[1];
        ull w0 = pack2(wv.x, wv.x), w1 = pack2(wv.y, wv.y);
        ull w2 = pack2(wv.z, wv.z), w3 = pack2(wv.w, wv.w);
        acc[0][0] = fma2(w0, x0, acc[0][0]); acc[0][1] = fma2(w0, x1, acc[0][1]);
        acc[1][0] = fma2(w1, x0, acc[1][0]); acc[1][1] = fma2(w1, x1, acc[1][1]);
        acc[2][0] = fma2(w2, x0, acc[2][0]); acc[2][1] = fma2(w2, x1, acc[2][1]);
        acc[3][0] = fma2(w3, x0, acc[3][0]); acc[3][1] = fma2(w3, x1, acc[3][1]);
    }

#pragma unroll
    for (int i = 0; i < 4; i++) {
        int o = og * 4 + i;
        float bv = bias[o];
        float4 res = *(const float4*)(g_proj + ((size_t)b * 128 + o) * HWALL + p0 + pg * 4);
        float2 u0 = unpk(acc[i][0]), u1 = unpk(acc[i][1]);
        float4 r = make_float4(u0.x + bv + res.x, u0.y + bv + res.y,
                               u1.x + bv + res.z, u1.y + bv + res.w);
        *(float4*)(g_fused + ((size_t)b * 128 + 64 + o) * HWALL + p0 + pg * 4) = r;
    }
}

// ---------------- gate finalize (hidden in g_resp reused, [B,32,HW]) ---------
__global__ void __launch_bounds__(256) gate_finalize(const float* __restrict__ w2,
                                                     const float* __restrict__ b2) {
    int b = blockIdx.y;
    int p = blockIdx.x * 256 + threadIdx.x;
    __shared__ float w2s[32];
    if (threadIdx.x < 32) w2s[threadIdx.x] = w2[threadIdx.x];
    __syncthreads();
    float s = b2[0];
#pragma unroll
    for (int j = 0; j < 32; j++)
        s += fmaxf(g_resp[((size_t)b * 32 + j) * HWALL + p], 0.0f) * w2s[j];
    float sg = sigmoidf(s);
#pragma unroll
    for (int off = 16; off > 0; off >>= 1)
        sg += __shfl_down_sync(0xffffffffu, sg, off);
    __shared__ float red[8];
    int w = threadIdx.x >> 5;
    if ((threadIdx.x & 31) == 0) red[w] = sg;
    __syncthreads();
    if (threadIdx.x == 0) {
        float t = 0.f;
#pragma unroll
        for (int ww = 0; ww < 8; ww++) t += red[ww];
        atomicAdd(&g_gatesum, t);
    }
}

// ---------------- depthwise 3x3 SAME, 16-row strips --------------------------
__global__ void __launch_bounds__(256) dw3x3_strip(const float* __restrict__ w) {
    int strip = blockIdx.x;           // 0..15
    int bc = blockIdx.y;              // b*192 + ch
    int ch = bc % 192;
    const float* inp = g_qkv + (size_t)bc * HWALL;
    float* outp = g_qkv2 + (size_t)bc * HWALL;
    __shared__ float s[3][258];
    int t = threadIdx.x;
    int y0 = strip * 16;

    if (t < 6) s[t / 2][(t & 1) ? 257 : 0] = 0.f;   // halo columns, always zero
    float wreg[9];
#pragma unroll
    for (int i = 0; i < 9; i++) wreg[i] = __ldg(&w[ch * 9 + i]);

#pragma unroll
    for (int r = 0; r < 2; r++) {
        int row = y0 - 1 + r;
        s[r][t + 1] = (row >= 0) ? inp[row * 256 + t] : 0.0f;
    }
    for (int y = 0; y < 16; y++) {
        int sn = (y + 2) % 3;
        int row = y0 + y + 1;
        __syncthreads();
        s[sn][t + 1] = (row < 256) ? inp[row * 256 + t] : 0.0f;
        __syncthreads();
        int s0 = y % 3, s1 = (y + 1) % 3, s2 = sn;
        float acc = 0.f;
#pragma unroll
        for (int dx = 0; dx < 3; dx++) acc += wreg[0 * 3 + dx] * s[s0][t + dx];
#pragma unroll
        for (int dx = 0; dx < 3; dx++) acc += wreg[1 * 3 + dx] * s[s1][t + dx];
#pragma unroll
        for (int dx = 0; dx < 3; dx++) acc += wreg[2 * 3 + dx] * s[s2][t + dx];
        outp[(y0 + y) * 256 + t] = acc;
    }
}

// ---------------- gram: q.k^T + norms (R2-exact) -----------------------------
__global__ void __launch_bounds__(256) gram_kernel() {
    int bh = blockIdx.y;
    int b = bh >> 3, h = bh & 7;
    const float* qb = g_qkv2 + ((size_t)b * 192 + h * 8) * HWALL;
    const float* kb = qb + (size_t)64 * HWALL;
    float acc[8][8], qs[8], ks[8];
#pragma unroll
    for (int i = 0; i < 8; i++) {
        qs[i] = 0.f; ks[i] = 0.f;
#pragma unroll
        for (int j = 0; j < 8; j++) acc[i][j] = 0.f;
    }
    int base = blockIdx.x * 1024;
#pragma unroll
    for (int it = 0; it < 4; it++) {
        int p = base + it * 256 + threadIdx.x;
        float qv[8], kv[8];
#pragma unroll
        for (int i = 0; i < 8; i++) {
            qv[i] = qb[(size_t)i * HWALL + p];
            kv[i] = kb[(size_t)i * HWALL + p];
        }
#pragma unroll
        for (int i = 0; i < 8; i++) {
            qs[i] += qv[i] * qv[i];
            ks[i] += kv[i] * kv[i];
#pragma unroll
            for (int j = 0; j < 8; j++) acc[i][j] += qv[i] * kv[j];
        }
    }
    __shared__ float red[8][80];
    int w = threadIdx.x >> 5, l = threadIdx.x & 31;
#pragma unroll
    for (int v = 0; v < 80; v++) {
        float val = (v < 64) ? acc[v >> 3][v & 7] : ((v < 72) ? qs[v - 64] : ks[v - 72]);
#pragma unroll
        for (int off = 16; off > 0; off >>= 1)
            val += __shfl_down_sync(0xffffffffu, val, off);
        if (l == 0) red[w][v] = val;
    }
    __syncthreads();
    for (int v = threadIdx.x; v < 80; v += 256) {
        float s = 0.f;
#pragma unroll
        for (int ww = 0; ww < 8; ww++) s += red[ww][v];
        atomicAdd(&g_gram[bh * 80 + v], s);
    }
}

// ---------------- attn finalize: normalize, top-k mask, softmax --------------
__global__ void attn_finalize(const float* __restrict__ temp) {
    __shared__ float kdyn_s;
    int t = threadIdx.x;    // 256 rows = 4*8*8
    if (t == 0) {
        float mean = g_gatesum * (1.0f / (BATCH * (float)HWALL));
        float kd = floorf(8.0f * mean);
        kdyn_s = fminf(fmaxf(kd, 1.0f), 8.0f);
    }
    __syncthreads();
    int b = t >> 6, h = (t >> 3) & 7, i = t & 7;
    const float* G = &g_gram[(b * 8 + h) * 80];
    float qn = fmaxf(sqrtf(G[64 + i]), 1e-12f);
    float tp = temp[h];
    float a[8];
#pragma unroll
    for (int j = 0; j < 8; j++) {
        float kn = fmaxf(sqrtf(G[72 + j]), 1e-12f);
        a[j] = G[i * 8 + j] / (qn * kn) * tp;
    }
    float kd = kdyn_s;
    float m[8];
#pragma unroll
    for (int j = 0; j < 8; j++) {
        int rank = 0;
#pragma unroll
        for (int q = 0; q < 8; q++)
            rank += (a[q] > a[j]) || (a[q] == a[j] && q < j);
        m[j] = ((float)rank < kd) ? a[j] : -INFINITY;
    }
    float mx = -INFINITY;
#pragma unroll
    for (int j = 0; j < 8; j++) mx = fmaxf(mx, m[j]);
    float es[8], ssum = 0.f;
#pragma unroll
    for (int j = 0; j < 8; j++) { es[j] = __expf(m[j] - mx); ssum += es[j]; }
    float inv = 1.0f / ssum;
#pragma unroll
    for (int j = 0; j < 8; j++)
        g_attn[((b * 8 + h) * 8 + i) * 8 + j] = es[j] * inv;
}

// ---------------- out = attn @ v * scales.sum() (R2-exact) -------------------
__global__ void __launch_bounds__(256) attn_apply(const float* __restrict__ scales) {
    int b = blockIdx.y;
    int p = blockIdx.x * 256 + threadIdx.x;
    __shared__ float As[512];
    __shared__ float ss;
    for (int i = threadIdx.x; i < 512; i += 256) As[i] = g_attn[b * 512 + i];
    if (threadIdx.x == 0) ss = scales[0] + scales[1] + scales[2] + scales[3];
    __syncthreads();
    const float* vb = g_qkv2 + ((size_t)b * 192 + 128) * HWALL;
    float* ob = g_fused + (size_t)b * 128 * HWALL;
#pragma unroll
    for (int h = 0; h < 8; h++) {
        float vv[8];
#pragma unroll
        for (int j = 0; j < 8; j++) vv[j] = vb[(size_t)(h * 8 + j) * HWALL + p];
#pragma unroll
        for (int i = 0; i < 8; i++) {
            float s = 0.f;
#pragma unroll
            for (int j = 0; j < 8; j++) s += As[(h * 8 + i) * 8 + j] * vv[j];
            ob[(size_t)(h * 8 + i) * HWALL + p] = s * ss;
        }
    }
}

// ---------------- launch ------------------------------------------------------
extern "C" void kernel_launch(void* const* d_in, const int* in_sizes, int n_in,
                              void* d_out, int out_size) {
    const float* x      = (const float*)d_in[0];
    const float* ip_w   = (const float*)d_in[1];
    const float* pre_w  = (const float*)d_in[2];
    const float* pre_b  = (const float*)d_in[3];
    const float* w1     = (const float*)d_in[4];
    const float* b1     = (const float*)d_in[5];
    const float* w2     = (const float*)d_in[6];
    const float* b2     = (const float*)d_in[7];
    const float* swp    = (const float*)d_in[8];
    const float* sbp    = (const float*)d_in[9];
    const float* post_w = (const float*)d_in[10];
    const float* post_b = (const float*)d_in[11];
    const float* qkv_w  = (const float*)d_in[12];
    const float* dw_w   = (const float*)d_in[13];
    const float* g1w    = (const float*)d_in[14];
    const float* g1b    = (const float*)d_in[15];
    const float* g2w    = (const float*)d_in[16];
    const float* g2b    = (const float*)d_in[17];
    const float* temp   = (const float*)d_in[18];
    const float* scales = (const float*)d_in[19];
    const float* po_w   = (const float*)d_in[20];

    void *p_proj, *p_xp, *p_resp, *p_qkv, *p_fused;
    void *p_wip, *p_wpre, *p_wqkv, *p_wg1, *p_wpo;
    cudaGetSymbolAddress(&p_proj, g_proj);
    cudaGetSymbolAddress(&p_xp, g_xp);
    cudaGetSymbolAddress(&p_resp, g_resp);
    cudaGetSymbolAddress(&p_qkv, g_qkv);
    cudaGetSymbolAddress(&p_fused, g_fused);
    cudaGetSymbolAddress(&p_wip, g_wt_ip);
    cudaGetSymbolAddress(&p_wpre, g_wt_pre);
    cudaGetSymbolAddress(&p_wqkv, g_wt_qkv);
    cudaGetSymbolAddress(&p_wg1, g_wt_g1);
    cudaGetSymbolAddress(&p_wpo, g_wt_po);

    zero_small<<<10, 256>>>();
    transpose_all<<<216, 256>>>(ip_w, pre_w, post_w, qkv_w, g1w, po_w);

    const long long S128 = 128LL * HWALL, S64 = 64LL * HWALL,
                    S192 = 192LL * HWALL, S32 = 32LL * HWALL;

    // 1) input projection: x -> proj
    conv1x1_gemm_t<128><<<dim3(512, 2, 4), 256>>>(x, (float*)p_wip, nullptr, (float*)p_proj,
                                                  128, S128, 0, S128, 0);
    // 2) lgce pre-conv: lb -> xp
    conv1x1_gemm_t<64><<<dim3(512, 1, 4), 256>>>((float*)p_proj, (float*)p_wpre, pre_b, (float*)p_xp,
                                                 64, S128, 0, S64, 0);
    pool_mean<<<256, 256>>>();
    compute_cw<<<1, 256>>>(w1, b1, w2, b2);
    resp_kernel<<<dim3(256, 4), 256>>>(swp, sbp);
    // 3) masked post-conv + residual -> fused[64:]
    conv1x1_maskres<<<dim3(1024, 1, 4), 256>>>(post_b);
    // gate hidden: gb -> g_resp (reused) [B,32,HW]
    conv1x1_gemm_t<64><<<dim3(512, 1, 4), 256>>>((float*)p_proj, (float*)p_wg1, g1b, (float*)p_resp,
                                                 32, S128, 64, S32, 0);
    gate_finalize<<<dim3(256, 4), 256>>>(g2w, g2b);
    // qkv: gb -> qkv
    conv1x1_gemm_t<64><<<dim3(512, 3, 4), 256>>>((float*)p_proj, (float*)p_wqkv, nullptr, (float*)p_qkv,
                                                 192, S128, 64, S192, 0);
    dw3x3_strip<<<dim3(16, BATCH * 192), 256>>>(dw_w);
    gram_kernel<<<dim3(64, 32), 256>>>();
    attn_finalize<<<1, 256>>>(temp);
    attn_apply<<<dim3(256, 4), 256>>>(scales);
    // final projection
    conv1x1_gemm_t<128><<<dim3(512, 2, 4), 256>>>((float*)p_fused, (float*)p_wpo, nullptr, (float*)d_out,
                                                  128, S128, 0, S128, 0);
}

// round 9
// speedup vs baseline: 1.5202x; 1.5202x over previous
#include <cuda_runtime.h>
#include <math.h>

#define HWALL 65536
#define BATCH 4

typedef unsigned long long ull;

// ---------------- scratch (device globals; no allocations allowed) ----------
__device__ float g_proj [BATCH * 128 * HWALL];   // input_proj output (lb | gb)
__device__ float g_xp   [BATCH *  64 * HWALL];   // lgce pre-conv output
__device__ float g_resp [BATCH *  64 * HWALL];   // resp
__device__ float g_qkv  [BATCH * 192 * HWALL];   // qkv pre-dw
__device__ float g_qkv2 [BATCH * 192 * HWALL];   // qkv post-dw
__device__ float g_fused[BATCH * 128 * HWALL];   // [attn_out | lgce_out]

__device__ float g_wt_ip  [128 * 128];
__device__ float g_wt_pre [ 64 *  64];
__device__ float g_wt_post[ 64 *  64];
__device__ float g_wt_qkv [ 64 * 192];
__device__ float g_wt_po  [128 * 128];

__device__ float g_pooled [BATCH * 64];
__device__ float g_cw     [BATCH * 64];
__device__ float g_respsum[BATCH * 8];
__device__ float g_gatesum;
__device__ float g_gram   [BATCH * 8 * 80];   // per (b,h): 64 gram + 8 qsq + 8 ksq
__device__ float g_attn   [BATCH * 8 * 64];

__device__ __forceinline__ float sigmoidf(float x) {
    return 1.0f / (1.0f + __expf(-x));
}

__device__ __forceinline__ ull pack2(float a, float b) {
    ull r; asm("mov.b64 %0, {%1, %2};" : "=l"(r) : "f"(a), "f"(b)); return r;
}
__device__ __forceinline__ ull fma2(ull a, ull b, ull c) {
    ull d; asm("fma.rn.f32x2 %0, %1, %2, %3;" : "=l"(d) : "l"(a), "l"(b), "l"(c)); return d;
}
__device__ __forceinline__ float2 unpk(ull v) {
    float2 f; asm("mov.b64 {%0, %1}, %2;" : "=f"(f.x), "=f"(f.y) : "l"(v)); return f;
}

__device__ __forceinline__ void cp_async16(void* smem_dst, const void* gptr) {
    unsigned sa = (unsigned)__cvta_generic_to_shared(smem_dst);
    asm volatile("cp.async.ca.shared.global [%0], [%1], 16;" :: "r"(sa), "l"(gptr));
}
__device__ __forceinline__ void cp_commit() {
    asm volatile("cp.async.commit_group;");
}
template<int N>
__device__ __forceinline__ void cp_wait() {
    asm volatile("cp.async.wait_group %0;" :: "n"(N));
}

// ---------------- small setup kernels ----------------------------------------
__global__ void zero_small() {
    int t = blockIdx.x * 256 + threadIdx.x;
    if (t < BATCH * 64) g_pooled[t] = 0.f;
    if (t < BATCH * 8)  g_respsum[t] = 0.f;
    if (t == 0)         g_gatesum = 0.f;
    if (t < BATCH * 8 * 80) g_gram[t] = 0.f;
}

__global__ void transpose_all(const float* __restrict__ ip, const float* __restrict__ pre,
                              const float* __restrict__ post, const float* __restrict__ qkv,
                              const float* __restrict__ po) {
    int i = blockIdx.x * 256 + threadIdx.x;
    if (i < 16384) { int o = i >> 7, c = i & 127; g_wt_ip[c * 128 + o] = ip[i]; return; }
    i -= 16384;
    if (i < 4096)  { int o = i >> 6, c = i & 63;  g_wt_pre[c * 64 + o] = pre[i]; return; }
    i -= 4096;
    if (i < 4096)  { int o = i >> 6, c = i & 63;  g_wt_post[c * 64 + o] = post[i]; return; }
    i -= 4096;
    if (i < 12288) { int o = i >> 6, c = i & 63;  g_wt_qkv[c * 192 + o] = qkv[i]; return; }
    i -= 12288;
    if (i < 16384) { int o = i >> 7, c = i & 127; g_wt_po[c * 128 + o] = po[i]; }
}

// ---------------- conv1x1 GEMM (R6-exact): FFMA2, cp.async double-buffer -----
// out[o,p] = sum_c in[c,p]*W[o,c]; wt transposed wt[c*COUT+o].
template<int CIN>
__global__ void __launch_bounds__(256) conv1x1_gemm_t(
    const float* __restrict__ in, const float* __restrict__ wt,
    const float* __restrict__ bias, float* __restrict__ out,
    int COUT, long long in_bstride, int in_coff,
    long long out_bstride, int out_coff)
{
    __shared__ float Ws[CIN * 64];
    __shared__ float Xs[2][16 * 128];
    int b  = blockIdx.z;
    int p0 = blockIdx.x * 128;
    int o0 = blockIdx.y * 64;
    int tid = threadIdx.x;
    const float* inb = in + (size_t)b * in_bstride + (size_t)in_coff * HWALL;

    for (int i = tid; i < CIN * 64; i += 256) {
        int c = i >> 6, ol = i & 63;
        int o = o0 + ol;
        Ws[i] = (o < COUT) ? wt[c * COUT + o] : 0.0f;
    }

    int og = tid & 15, pg = tid >> 4;
    int xr = tid >> 4, xc = (tid & 15) * 8;

    // prefetch chunk 0
    {
        const float* src = inb + (size_t)xr * HWALL + p0 + xc;
        cp_async16(&Xs[0][xr * 128 + xc],     src);
        cp_async16(&Xs[0][xr * 128 + xc + 4], src + 4);
        cp_commit();
    }

    ull acc[4][4];
#pragma unroll
    for (int i = 0; i < 4; i++)
#pragma unroll
        for (int j = 0; j < 4; j++) acc[i][j] = 0ull;

    constexpr int NC = CIN / 16;
#pragma unroll
    for (int c = 0; c < NC; c++) {
        if (c + 1 < NC) {
            const float* src = inb + (size_t)((c + 1) * 16 + xr) * HWALL + p0 + xc;
            cp_async16(&Xs[(c + 1) & 1][xr * 128 + xc],     src);
            cp_async16(&Xs[(c + 1) & 1][xr * 128 + xc + 4], src + 4);
            cp_commit();
            cp_wait<1>();
        } else {
            cp_wait<0>();
        }
        __syncthreads();
        const float* Xc = Xs[c & 1];
#pragma unroll
        for (int k = 0; k < 16; k++) {
            float4 wv = *(const float4*)&Ws[(c * 16 + k) * 64 + og * 4];
            const ull* xp2 = (const ull*)&Xc[k * 128 + pg * 8];
            ull x0 = xp2[0], x1 = xp2[1], x2 = xp2[2], x3 = xp2[3];
            ull w0 = pack2(wv.x, wv.x), w1 = pack2(wv.y, wv.y);
            ull w2 = pack2(wv.z, wv.z), w3 = pack2(wv.w, wv.w);
            acc[0][0] = fma2(w0, x0, acc[0][0]); acc[0][1] = fma2(w0, x1, acc[0][1]);
            acc[0][2] = fma2(w0, x2, acc[0][2]); acc[0][3] = fma2(w0, x3, acc[0][3]);
            acc[1][0] = fma2(w1, x0, acc[1][0]); acc[1][1] = fma2(w1, x1, acc[1][1]);
            acc[1][2] = fma2(w1, x2, acc[1][2]); acc[1][3] = fma2(w1, x3, acc[1][3]);
            acc[2][0] = fma2(w2, x0, acc[2][0]); acc[2][1] = fma2(w2, x1, acc[2][1]);
            acc[2][2] = fma2(w2, x2, acc[2][2]); acc[2][3] = fma2(w2, x3, acc[2][3]);
            acc[3][0] = fma2(w3, x0, acc[3][0]); acc[3][1] = fma2(w3, x1, acc[3][1]);
            acc[3][2] = fma2(w3, x2, acc[3][2]); acc[3][3] = fma2(w3, x3, acc[3][3]);
        }
        __syncthreads();
    }

    float* outb = out + (size_t)b * out_bstride + (size_t)out_coff * HWALL;
#pragma unroll
    for (int i = 0; i < 4; i++) {
        int o = o0 + og * 4 + i;
        if (o < COUT) {
            float bv = bias ? bias[o] : 0.0f;
            float2 u0 = unpk(acc[i][0]), u1 = unpk(acc[i][1]);
            float2 u2 = unpk(acc[i][2]), u3 = unpk(acc[i][3]);
            float4 r0 = make_float4(u0.x + bv, u0.y + bv, u1.x + bv, u1.y + bv);
            float4 r1 = make_float4(u2.x + bv, u2.y + bv, u3.x + bv, u3.y + bv);
            float* dst = outb + (size_t)o * HWALL + p0 + pg * 8;
            *(float4*)(dst)     = r0;
            *(float4*)(dst + 4) = r1;
        }
    }
}

// ---------------- LGCE pooling (R2-exact) -------------------------------------
__global__ void pool_mean() {
    int bc = blockIdx.x;   // 0..255 = b*64+c
    const float* p = g_xp + (size_t)bc * HWALL;
    float s = 0.f;
    for (int i = threadIdx.x; i < HWALL / 4; i += 256) {
        float4 v = ((const float4*)p)[i];
        s += v.x + v.y + v.z + v.w;
    }
    __shared__ float sm[256];
    sm[threadIdx.x] = s; __syncthreads();
    for (int st = 128; st; st >>= 1) {
        if (threadIdx.x < st) sm[threadIdx.x] += sm[threadIdx.x + st];
        __syncthreads();
    }
    if (threadIdx.x == 0) g_pooled[bc] = sm[0];
}

__global__ void compute_cw(const float* __restrict__ w1, const float* __restrict__ b1,
                           const float* __restrict__ w2, const float* __restrict__ b2) {
    int t = threadIdx.x;               // 256 = 4*8*8
    int b = t >> 6, gc = t & 63, g = gc >> 3, c = gc & 7;
    float hid[2];
#pragma unroll
    for (int hh = 0; hh < 2; hh++) {
        float s = b1[g * 2 + hh];
#pragma unroll
        for (int cc = 0; cc < 8; cc++)
            s += (g_pooled[b * 64 + g * 8 + cc] * (1.0f / HWALL)) * w1[(g * 2 + hh) * 8 + cc];
        hid[hh] = fmaxf(s, 0.0f);
    }
    float s2 = b2[g * 8 + c] + hid[0] * w2[(g * 8 + c) * 2] + hid[1] * w2[(g * 8 + c) * 2 + 1];
    g_cw[b * 64 + gc] = sigmoidf(s2);
}

// ---------------- resp: compute, store (g_resp), reduce sums (R2-exact) ------
__global__ void __launch_bounds__(256) resp_kernel(const float* __restrict__ sw,
                                                   const float* __restrict__ sb) {
    int b = blockIdx.y;
    int p = blockIdx.x * 256 + threadIdx.x;
    __shared__ float cws[64], sws[64], sbs[8];
    if (threadIdx.x < 64) { cws[threadIdx.x] = g_cw[b * 64 + threadIdx.x]; sws[threadIdx.x] = sw[threadIdx.x]; }
    if (threadIdx.x < 8) sbs[threadIdx.x] = sb[threadIdx.x];
    __syncthreads();

    float rsum[8];
#pragma unroll
    for (int g = 0; g < 8; g++) {
        float xc[8];
        float sa = sbs[g];
#pragma unroll
        for (int c = 0; c < 8; c++) {
            float v = g_xp[((size_t)b * 64 + g * 8 + c) * HWALL + p];
            xc[c] = v * cws[g * 8 + c];
            sa += sws[g * 8 + c] * xc[c];
        }
        float sp = sigmoidf(sa);
        float rs = 0.f;
#pragma unroll
        for (int c = 0; c < 8; c++) {
            float r = sigmoidf(xc[c] * sp);
            g_resp[((size_t)b * 64 + g * 8 + c) * HWALL + p] = r;
            rs += r;
        }
        rsum[g] = rs;
    }
#pragma unroll
    for (int g = 0; g < 8; g++)
#pragma unroll
        for (int off = 16; off > 0; off >>= 1)
            rsum[g] += __shfl_down_sync(0xffffffffu, rsum[g], off);

    __shared__ float red[8][8];
    int w = threadIdx.x >> 5, l = threadIdx.x & 31;
    if (l == 0)
#pragma unroll
        for (int g = 0; g < 8; g++) red[w][g] = rsum[g];
    __syncthreads();
    if (threadIdx.x < 8) {
        float s = 0.f;
#pragma unroll
        for (int ww = 0; ww < 8; ww++) s += red[ww][threadIdx.x];
        atomicAdd(&g_respsum[b * 8 + threadIdx.x], s);
    }
}

// ---------------- masked post-conv + residual, 128-px tiles ------------------
// Mask values and GEMM chain identical to R6 (bit-identical results).
__global__ void __launch_bounds__(256) conv1x1_maskres(const float* __restrict__ bias)
{
    __shared__ float Ws[64 * 64];      // 16 KB
    __shared__ float Xm[64 * 128];     // 32 KB
    __shared__ float thr_s[8];
    int b  = blockIdx.z;
    int p0 = blockIdx.x * 128;
    int tid = threadIdx.x;

    if (tid < 8) thr_s[tid] = g_respsum[b * 8 + tid] * (1.0f / (8.0f * HWALL));
    for (int i = tid; i < 64 * 64; i += 256) {
        int c = i >> 6, o = i & 63;
        Ws[i] = g_wt_post[c * 64 + o];
    }
    __syncthreads();

    // mask compute: 2048 float4s over 64ch x 128px; 8 per thread
    {
        const float* xpb = g_xp   + (size_t)b * 64 * HWALL;
        const float* rsb = g_resp + (size_t)b * 64 * HWALL;
#pragma unroll
        for (int i = 0; i < 8; i++) {
            int f = i * 256 + tid;
            int ch = f >> 5, px4 = (f & 31) * 4;
            float t = thr_s[ch >> 3];
            float4 xv = *(const float4*)(xpb + (size_t)ch * HWALL + p0 + px4);
            float4 rv = *(const float4*)(rsb + (size_t)ch * HWALL + p0 + px4);
            xv.x *= (rv.x > t) ? 1.0f : rv.x;
            xv.y *= (rv.y > t) ? 1.0f : rv.y;
            xv.z *= (rv.z > t) ? 1.0f : rv.z;
            xv.w *= (rv.w > t) ? 1.0f : rv.w;
            *(float4*)&Xm[ch * 128 + px4] = xv;
        }
    }
    __syncthreads();

    int og = tid & 15, pg = tid >> 4;
    ull acc[4][4];
#pragma unroll
    for (int i = 0; i < 4; i++)
#pragma unroll
        for (int j = 0; j < 4; j++) acc[i][j] = 0ull;

#pragma unroll 8
    for (int k = 0; k < 64; k++) {
        float4 wv = *(const float4*)&Ws[k * 64 + og * 4];
        const ull* xp2 = (const ull*)&Xm[k * 128 + pg * 8];
        ull x0 = xp2[0], x1 = xp2[1], x2 = xp2[2], x3 = xp2[3];
        ull w0 = pack2(wv.x, wv.x), w1 = pack2(wv.y, wv.y);
        ull w2 = pack2(wv.z, wv.z), w3 = pack2(wv.w, wv.w);
        acc[0][0] = fma2(w0, x0, acc[0][0]); acc[0][1] = fma2(w0, x1, acc[0][1]);
        acc[0][2] = fma2(w0, x2, acc[0][2]); acc[0][3] = fma2(w0, x3, acc[0][3]);
        acc[1][0] = fma2(w1, x0, acc[1][0]); acc[1][1] = fma2(w1, x1, acc[1][1]);
        acc[1][2] = fma2(w1, x2, acc[1][2]); acc[1][3] = fma2(w1, x3, acc[1][3]);
        acc[2][0] = fma2(w2, x0, acc[2][0]); acc[2][1] = fma2(w2, x1, acc[2][1]);
        acc[2][2] = fma2(w2, x2, acc[2][2]); acc[2][3] = fma2(w2, x3, acc[2][3]);
        acc[3][0] = fma2(w3, x0, acc[3][0]); acc[3][1] = fma2(w3, x1, acc[3][1]);
        acc[3][2] = fma2(w3, x2, acc[3][2]); acc[3][3] = fma2(w3, x3, acc[3][3]);
    }

#pragma unroll
    for (int i = 0; i < 4; i++) {
        int o = og * 4 + i;
        float bv = bias[o];
        const float* resp_ = g_proj + ((size_t)b * 128 + o) * HWALL + p0 + pg * 8;
        float4 ra = *(const float4*)(resp_);
        float4 rb = *(const float4*)(resp_ + 4);
        float2 u0 = unpk(acc[i][0]), u1 = unpk(acc[i][1]);
        float2 u2 = unpk(acc[i][2]), u3 = unpk(acc[i][3]);
        float4 w0_ = make_float4(u0.x + bv + ra.x, u0.y + bv + ra.y,
                                 u1.x + bv + ra.z, u1.y + bv + ra.w);
        float4 w1_ = make_float4(u2.x + bv + rb.x, u2.y + bv + rb.y,
                                 u3.x + bv + rb.z, u3.y + bv + rb.w);
        float* dst = g_fused + ((size_t)b * 128 + 64 + o) * HWALL + p0 + pg * 8;
        *(float4*)(dst)     = w0_;
        *(float4*)(dst + 4) = w1_;
    }
}

// ---------------- fused gate: hidden in regs, same partial-sum grouping ------
// hidden[i] chain = k-ascending FMA from 0, + bias (matches R6 GEMM chain);
// relu/dot/sigmoid and the 256-px block reduction match R6 gate_finalize.
__global__ void __launch_bounds__(256) gate_kernel(
    const float* __restrict__ g1w, const float* __restrict__ g1b,
    const float* __restrict__ g2w, const float* __restrict__ g2b)
{
    int b = blockIdx.y;
    int p = blockIdx.x * 256 + threadIdx.x;
    __shared__ float W1[32 * 64];   // raw layout: W1[i*64+j]
    __shared__ float b1s[32], w2s[32];
    for (int i = threadIdx.x; i < 32 * 64; i += 256) W1[i] = g1w[i];
    if (threadIdx.x < 32) { b1s[threadIdx.x] = g1b[threadIdx.x]; w2s[threadIdx.x] = g2w[threadIdx.x]; }
    __syncthreads();

    const float* gbp = g_proj + (size_t)b * 128 * HWALL + (size_t)64 * HWALL;
    float x[64];
#pragma unroll
    for (int j = 0; j < 64; j++) x[j] = gbp[(size_t)j * HWALL + p];

    float s = g2b[0];
#pragma unroll 4
    for (int i = 0; i < 32; i++) {
        float acc = 0.f;
#pragma unroll
        for (int j = 0; j < 64; j++) acc = fmaf(x[j], W1[i * 64 + j], acc);
        float h = acc + b1s[i];
        s += fmaxf(h, 0.0f) * w2s[i];
    }
    float sg = sigmoidf(s);
#pragma unroll
    for (int off = 16; off > 0; off >>= 1)
        sg += __shfl_down_sync(0xffffffffu, sg, off);
    __shared__ float red[8];
    int w = threadIdx.x >> 5;
    if ((threadIdx.x & 31) == 0) red[w] = sg;
    __syncthreads();
    if (threadIdx.x == 0) {
        float t = 0.f;
#pragma unroll
        for (int ww = 0; ww < 8; ww++) t += red[ww];
        atomicAdd(&g_gatesum, t);
    }
}

// ---------------- depthwise 3x3 SAME, 16-row strips --------------------------
__global__ void __launch_bounds__(256) dw3x3_strip(const float* __restrict__ w) {
    int strip = blockIdx.x;           // 0..15
    int bc = blockIdx.y;              // b*192 + ch
    int ch = bc % 192;
    const float* inp = g_qkv + (size_t)bc * HWALL;
    float* outp = g_qkv2 + (size_t)bc * HWALL;
    __shared__ float s[3][258];
    int t = threadIdx.x;
    int y0 = strip * 16;

    if (t < 6) s[t / 2][(t & 1) ? 257 : 0] = 0.f;   // halo columns, always zero
    float wreg[9];
#pragma unroll
    for (int i = 0; i < 9; i++) wreg[i] = __ldg(&w[ch * 9 + i]);

#pragma unroll
    for (int r = 0; r < 2; r++) {
        int row = y0 - 1 + r;
        s[r][t + 1] = (row >= 0) ? inp[row * 256 + t] : 0.0f;
    }
    for (int y = 0; y < 16; y++) {
        int sn = (y + 2) % 3;
        int row = y0 + y + 1;
        __syncthreads();
        s[sn][t + 1] = (row < 256) ? inp[row * 256 + t] : 0.0f;
        __syncthreads();
        int s0 = y % 3, s1 = (y + 1) % 3, s2 = sn;
        float acc = 0.f;
#pragma unroll
        for (int dx = 0; dx < 3; dx++) acc += wreg[0 * 3 + dx] * s[s0][t + dx];
#pragma unroll
        for (int dx = 0; dx < 3; dx++) acc += wreg[1 * 3 + dx] * s[s1][t + dx];
#pragma unroll
        for (int dx = 0; dx < 3; dx++) acc += wreg[2 * 3 + dx] * s[s2][t + dx];
        outp[(y0 + y) * 256 + t] = acc;
    }
}

// ---------------- gram: q.k^T + norms (R2-exact) -----------------------------
__global__ void __launch_bounds__(256) gram_kernel() {
    int bh = blockIdx.y;
    int b = bh >> 3, h = bh & 7;
    const float* qb = g_qkv2 + ((size_t)b * 192 + h * 8) * HWALL;
    const float* kb = qb + (size_t)64 * HWALL;
    float acc[8][8], qs[8], ks[8];
#pragma unroll
    for (int i = 0; i < 8; i++) {
        qs[i] = 0.f; ks[i] = 0.f;
#pragma unroll
        for (int j = 0; j < 8; j++) acc[i][j] = 0.f;
    }
    int base = blockIdx.x * 1024;
#pragma unroll
    for (int it = 0; it < 4; it++) {
        int p = base + it * 256 + threadIdx.x;
        float qv[8], kv[8];
#pragma unroll
        for (int i = 0; i < 8; i++) {
            qv[i] = qb[(size_t)i * HWALL + p];
            kv[i] = kb[(size_t)i * HWALL + p];
        }
#pragma unroll
        for (int i = 0; i < 8; i++) {
            qs[i] += qv[i] * qv[i];
            ks[i] += kv[i] * kv[i];
#pragma unroll
            for (int j = 0; j < 8; j++) acc[i][j] += qv[i] * kv[j];
        }
    }
    __shared__ float red[8][80];
    int w = threadIdx.x >> 5, l = threadIdx.x & 31;
#pragma unroll
    for (int v = 0; v < 80; v++) {
        float val = (v < 64) ? acc[v >> 3][v & 7] : ((v < 72) ? qs[v - 64] : ks[v - 72]);
#pragma unroll
        for (int off = 16; off > 0; off >>= 1)
            val += __shfl_down_sync(0xffffffffu, val, off);
        if (l == 0) red[w][v] = val;
    }
    __syncthreads();
    for (int v = threadIdx.x; v < 80; v += 256) {
        float s = 0.f;
#pragma unroll
        for (int ww = 0; ww < 8; ww++) s += red[ww][v];
        atomicAdd(&g_gram[bh * 80 + v], s);
    }
}

// ---------------- attn finalize: normalize, top-k mask, softmax --------------
__global__ void attn_finalize(const float* __restrict__ temp) {
    __shared__ float kdyn_s;
    int t = threadIdx.x;    // 256 rows = 4*8*8
    if (t == 0) {
        float mean = g_gatesum * (1.0f / (BATCH * (float)HWALL));
        float kd = floorf(8.0f * mean);
        kdyn_s = fminf(fmaxf(kd, 1.0f), 8.0f);
    }
    __syncthreads();
    int b = t >> 6, h = (t >> 3) & 7, i = t & 7;
    const float* G = &g_gram[(b * 8 + h) * 80];
    float qn = fmaxf(sqrtf(G[64 + i]), 1e-12f);
    float tp = temp[h];
    float a[8];
#pragma unroll
    for (int j = 0; j < 8; j++) {
        float kn = fmaxf(sqrtf(G[72 + j]), 1e-12f);
        a[j] = G[i * 8 + j] / (qn * kn) * tp;
    }
    float kd = kdyn_s;
    float m[8];
#pragma unroll
    for (int j = 0; j < 8; j++) {
        int rank = 0;
#pragma unroll
        for (int q = 0; q < 8; q++)
            rank += (a[q] > a[j]) || (a[q] == a[j] && q < j);
        m[j] = ((float)rank < kd) ? a[j] : -INFINITY;
    }
    float mx = -INFINITY;
#pragma unroll
    for (int j = 0; j < 8; j++) mx = fmaxf(mx, m[j]);
    float es[8], ssum = 0.f;
#pragma unroll
    for (int j = 0; j < 8; j++) { es[j] = __expf(m[j] - mx); ssum += es[j]; }
    float inv = 1.0f / ssum;
#pragma unroll
    for (int j = 0; j < 8; j++)
        g_attn[((b * 8 + h) * 8 + i) * 8 + j] = es[j] * inv;
}

// ---------------- out = attn @ v * scales.sum() (R2-exact) -------------------
__global__ void __launch_bounds__(256) attn_apply(const float* __restrict__ scales) {
    int b = blockIdx.y;
    int p = blockIdx.x * 256 + threadIdx.x;
    __shared__ float As[512];
    __shared__ float ss;
    for (int i = threadIdx.x; i < 512; i += 256) As[i] = g_attn[b * 512 + i];
    if (threadIdx.x == 0) ss = scales[0] + scales[1] + scales[2] + scales[3];
    __syncthreads();
    const float* vb = g_qkv2 + ((size_t)b * 192 + 128) * HWALL;
    float* ob = g_fused + (size_t)b * 128 * HWALL;
#pragma unroll
    for (int h = 0; h < 8; h++) {
        float vv[8];
#pragma unroll
        for (int j = 0; j < 8; j++) vv[j] = vb[(size_t)(h * 8 + j) * HWALL + p];
#pragma unroll
        for (int i = 0; i < 8; i++) {
            float s = 0.f;
#pragma unroll
            for (int j = 0; j < 8; j++) s += As[(h * 8 + i) * 8 + j] * vv[j];
            ob[(size_t)(h * 8 + i) * HWALL + p] = s * ss;
        }
    }
}

// ---------------- launch ------------------------------------------------------
extern "C" void kernel_launch(void* const* d_in, const int* in_sizes, int n_in,
                              void* d_out, int out_size) {
    const float* x      = (const float*)d_in[0];
    const float* ip_w   = (const float*)d_in[1];
    const float* pre_w  = (const float*)d_in[2];
    const float* pre_b  = (const float*)d_in[3];
    const float* w1     = (const float*)d_in[4];
    const float* b1     = (const float*)d_in[5];
    const float* w2     = (const float*)d_in[6];
    const float* b2     = (const float*)d_in[7];
    const float* swp    = (const float*)d_in[8];
    const float* sbp    = (const float*)d_in[9];
    const float* post_w = (const float*)d_in[10];
    const float* post_b = (const float*)d_in[11];
    const float* qkv_w  = (const float*)d_in[12];
    const float* dw_w   = (const float*)d_in[13];
    const float* g1w    = (const float*)d_in[14];
    const float* g1b    = (const float*)d_in[15];
    const float* g2w    = (const float*)d_in[16];
    const float* g2b    = (const float*)d_in[17];
    const float* temp   = (const float*)d_in[18];
    const float* scales = (const float*)d_in[19];
    const float* po_w   = (const float*)d_in[20];

    void *p_proj, *p_xp, *p_qkv, *p_fused;
    void *p_wip, *p_wpre, *p_wqkv, *p_wpo;
    cudaGetSymbolAddress(&p_proj, g_proj);
    cudaGetSymbolAddress(&p_xp, g_xp);
    cudaGetSymbolAddress(&p_qkv, g_qkv);
    cudaGetSymbolAddress(&p_fused, g_fused);
    cudaGetSymbolAddress(&p_wip, g_wt_ip);
    cudaGetSymbolAddress(&p_wpre, g_wt_pre);
    cudaGetSymbolAddress(&p_wqkv, g_wt_qkv);
    cudaGetSymbolAddress(&p_wpo, g_wt_po);

    zero_small<<<10, 256>>>();
    transpose_all<<<208, 256>>>(ip_w, pre_w, post_w, qkv_w, po_w);

    const long long S128 = 128LL * HWALL, S64 = 64LL * HWALL, S192 = 192LL * HWALL;

    // 1) input projection: x -> proj
    conv1x1_gemm_t<128><<<dim3(512, 2, 4), 256>>>(x, (float*)p_wip, nullptr, (float*)p_proj,
                                                  128, S128, 0, S128, 0);
    // 2) lgce pre-conv: lb -> xp
    conv1x1_gemm_t<64><<<dim3(512, 1, 4), 256>>>((float*)p_proj, (float*)p_wpre, pre_b, (float*)p_xp,
                                                 64, S128, 0, S64, 0);
    pool_mean<<<256, 256>>>();
    compute_cw<<<1, 256>>>(w1, b1, w2, b2);
    resp_kernel<<<dim3(256, 4), 256>>>(swp, sbp);
    // 3) masked post-conv + residual -> fused[64:]
    conv1x1_maskres<<<dim3(512, 1, 4), 256>>>(post_b);
    // fused gate (hidden in registers)
    gate_kernel<<<dim3(256, 4), 256>>>(g1w, g1b, g2w, g2b);
    // qkv: gb -> qkv
    conv1x1_gemm_t<64><<<dim3(512, 3, 4), 256>>>((float*)p_proj, (float*)p_wqkv, nullptr, (float*)p_qkv,
                                                 192, S128, 64, S192, 0);
    dw3x3_strip<<<dim3(16, BATCH * 192), 256>>>(dw_w);
    gram_kernel<<<dim3(64, 32), 256>>>();
    attn_finalize<<<1, 256>>>(temp);
    attn_apply<<<dim3(256, 4), 256>>>(scales);
    // final projection
    conv1x1_gemm_t<128><<<dim3(512, 2, 4), 256>>>((float*)p_fused, (float*)p_wpo, nullptr, (float*)d_out,
                                                  128, S128, 0, S128, 0);
}